// round 8
// baseline (speedup 1.0000x reference)
#include <cuda_runtime.h>
#include <math.h>
#include <stdint.h>

#define NB 8192
#define KN 32
#define HD 1024
#define GRID 444                       // 148 SMs * 3 CTAs, one wave
#define NSLOTS 4
#define STAGE_ROWS 4
#define STAGE_FLOATS (STAGE_ROWS * HD)           // 4096 floats
#define STAGE_BYTES  (STAGE_FLOATS * 4)          // 16 KB
#define CHUNKS 8                                  // stages per batch (8*16KB = 128KB)
#define NTHREADS 288                              // 8 consumer warps + 1 producer warp
#define DYN_SMEM_BYTES ((NSLOTS * STAGE_FLOATS + 2 * HD) * 4)   // 64KB + 8KB

__device__ __forceinline__ uint32_t smem_u32(const void* p) {
    return (uint32_t)__cvta_generic_to_shared(p);
}
__device__ __forceinline__ void mbar_init(uint32_t mbar, uint32_t count) {
    asm volatile("mbarrier.init.shared::cta.b64 [%0], %1;"
                 :: "r"(mbar), "r"(count) : "memory");
}
__device__ __forceinline__ void mbar_expect_tx(uint32_t mbar, uint32_t bytes) {
    asm volatile("mbarrier.arrive.expect_tx.shared::cta.b64 _, [%0], %1;"
                 :: "r"(mbar), "r"(bytes) : "memory");
}
__device__ __forceinline__ void mbar_arrive(uint32_t mbar) {
    asm volatile("mbarrier.arrive.shared::cta.b64 _, [%0];"
                 :: "r"(mbar) : "memory");
}
__device__ __forceinline__ void bulk_g2s(uint32_t dst, const void* src,
                                         uint32_t bytes, uint32_t mbar) {
    asm volatile(
        "cp.async.bulk.shared::cta.global.mbarrier::complete_tx::bytes "
        "[%0], [%1], %2, [%3];"
        :: "r"(dst), "l"(src), "r"(bytes), "r"(mbar) : "memory");
}
__device__ __forceinline__ void mbar_wait(uint32_t mbar, uint32_t phase) {
    uint32_t done;
    do {
        asm volatile(
            "{\n\t.reg .pred p;\n\t"
            "mbarrier.try_wait.parity.acquire.cta.shared::cta.b64 p, [%1], %2, 0x989680;\n\t"
            "selp.b32 %0, 1, 0, p;\n\t}"
            : "=r"(done) : "r"(mbar), "r"(phase) : "memory");
    } while (!done);
}
#define CBAR() asm volatile("bar.sync 1, 256;" ::: "memory")   // consumer warps only

__global__ __launch_bounds__(NTHREADS, 3)
void mu_calc_kernel(
    const int*   __restrict__ vals,
    const float* __restrict__ distances,
    const float* __restrict__ cache_hidden,
    const float* __restrict__ hiddens,
    const float* __restrict__ W1,
    const float* __restrict__ b1,
    const float* __restrict__ W2,
    const float* __restrict__ b2,
    float*       __restrict__ out)
{
    extern __shared__ __align__(16) float dyn[];
    float* s_buf   = dyn;                           // 4 slots * 16 KB
    float* s_cache = dyn + NSLOTS * STAGE_FLOATS;   // 2 cache_hidden slots

    __shared__ float s_part[64];     // per-(chunk,warp) half-row partial sums
    __shared__ float s_cd[KN];
    __shared__ float s_x[96];
    __shared__ int   s_vals[KN];
    __shared__ float s_h2[64];
    __shared__ __align__(8) unsigned long long s_mbar[2 * NSLOTS]; // full[4], empty[4]

    const int tid  = threadIdx.x;
    const int warp = tid >> 5;
    const int lane = tid & 31;

    const uint32_t mbase = smem_u32(&s_mbar[0]);
    const uint32_t bufb  = smem_u32(s_buf);
    // full[s] = mbase + s*8 ; empty[s] = mbase + 32 + s*8

    const int b0 = blockIdx.x;
    const int nb = (NB - b0 + GRID - 1) / GRID;     // batches owned by this CTA

    // ---- init ----
    if (tid == 0) {
        #pragma unroll
        for (int s = 0; s < NSLOTS; s++) {
            mbar_init(mbase + s * 8, 1);            // full: single expect_tx arrive
            mbar_init(mbase + 32 + s * 8, 8);       // empty: 8 consumer warps
        }
        asm volatile("fence.proxy.async.shared::cta;" ::: "memory");
    }
    if (tid < 256)
        reinterpret_cast<float4*>(s_cache)[tid] =
            reinterpret_cast<const float4*>(cache_hidden + (size_t)b0 * HD)[tid];
    __syncthreads();    // the ONLY full-block barrier

    if (warp == 8) {
        // ================= PRODUCER WARP =================
        if (lane == 0) {
            const int TOT = CHUNKS * nb;
            for (int g = 0; g < TOT; g++) {
                const int slot = g & 3;
                if (g >= NSLOTS)
                    mbar_wait(mbase + 32 + slot * 8, ((g >> 2) + 1) & 1);
                const int b = b0 + (g >> 3) * GRID;
                const float* src = hiddens +
                    ((size_t)b * KN + (size_t)(g & 7) * STAGE_ROWS) * HD;
                const uint32_t fm = mbase + slot * 8;
                mbar_expect_tx(fm, STAGE_BYTES);
                bulk_g2s(bufb + slot * STAGE_BYTES, src, STAGE_BYTES, fm);
            }
        }
        return;
    }

    // ================= CONSUMER WARPS (0-7) =================
    const int rw = warp >> 1;        // row within stage (0..3)
    const int hw = warp & 1;         // half of the row (0/1)

    for (int i = 0; i < nb; i++) {
        const int b = b0 + i * GRID;

        if (tid < KN) {                       // warp 0
            s_vals[tid]   = vals[b * KN + tid];
            s_x[32 + tid] = distances[b * KN + tid];
        }

        // cache half-row -> registers (slot i&1)
        const float4* sc4 = reinterpret_cast<const float4*>(s_cache + (i & 1) * HD);
        float4 cv[4];
        #pragma unroll
        for (int j = 0; j < 4; j++) cv[j] = sc4[hw * 128 + lane + 32 * j];

        // prefetch next batch's cache row
        float4 cnext;
        const bool hasnext = (i + 1 < nb);
        if (hasnext)
            cnext = reinterpret_cast<const float4*>(
                cache_hidden + (size_t)(b + GRID) * HD)[tid];

        // ---- 8 stages of 4 rows; this warp does half of row rw ----
        for (int c = 0; c < CHUNKS; c++) {
            const int g    = i * CHUNKS + c;
            const int slot = g & 3;
            mbar_wait(mbase + slot * 8, (g >> 2) & 1);

            const float4* rowp = reinterpret_cast<const float4*>(
                s_buf + slot * STAGE_FLOATS + rw * HD) + hw * 128;
            float acc = 0.f;
            #pragma unroll
            for (int j = 0; j < 4; j++) {
                const float4 h = rowp[lane + 32 * j];
                const float4 cc = cv[j];
                float d;
                d = cc.x - h.x; acc = fmaf(d, d, acc);
                d = cc.y - h.y; acc = fmaf(d, d, acc);
                d = cc.z - h.z; acc = fmaf(d, d, acc);
                d = cc.w - h.w; acc = fmaf(d, d, acc);
            }
            #pragma unroll
            for (int o = 16; o > 0; o >>= 1)
                acc += __shfl_xor_sync(0xffffffffu, acc, o);
            if (lane == 0) {
                s_part[c * 8 + warp] = acc;
                mbar_arrive(mbase + 32 + slot * 8);   // free the slot
            }
        }
        CBAR();                                   // partials visible

        if (hasnext)
            reinterpret_cast<float4*>(s_cache + ((i + 1) & 1) * HD)[tid] = cnext;

        if (warp == 0) {
            // s_cd + labels (all in warp 0)
            const int base = (lane >> 2) * 8 + (lane & 3) * 2;
            const float cdk = sqrtf(s_part[base] + s_part[base + 1]);
            s_cd[lane] = cdk;
            s_x[lane]  = cdk;
            const int v = s_vals[lane];
            int flag = (v != 0) ? 1 : 0;
            for (int j = 0; j < lane; j++)
                if (s_vals[j] == v) flag = 0;
            int c = flag;
            #pragma unroll
            for (int o = 1; o < 32; o <<= 1) {
                int t = __shfl_up_sync(0xffffffffu, c, o);
                if (lane >= o) c += t;
            }
            s_x[64 + lane] = (float)c;
        }
        CBAR();                                   // s_x complete

        if (tid < 64) {
            const float* w = W1 + tid * 96;       // 24KB, L2-resident
            float a = b1[tid];
            #pragma unroll
            for (int j = 0; j < 96; j++)
                a = fmaf(s_x[j], __ldg(w + j), a);
            s_h2[tid] = tanhf(a) * __ldg(W2 + tid);
        }
        CBAR();                                   // h2 ready

        if (warp == 0) {
            float v = s_h2[lane] + s_h2[lane + 32];
            #pragma unroll
            for (int o = 16; o > 0; o >>= 1)
                v += __shfl_xor_sync(0xffffffffu, v, o);
            float sc = 5.0f / (1.0f + expf(-(v + b2[0])));
            sc = __shfl_sync(0xffffffffu, sc, 0);
            const float cd = s_cd[lane] * sc;
            out[(size_t)b * KN + lane]                   = cd;
            out[(size_t)NB * KN + (size_t)b * KN + lane] = s_x[32 + lane] + cd;
        }
        // no trailing barrier needed: next-iteration writes are ordered by
        // the three CBARs above relative to all readers.
    }
}

extern "C" void kernel_launch(void* const* d_in, const int* in_sizes, int n_in,
                              void* d_out, int out_size) {
    const int*   vals         = (const int*)  d_in[0];
    const float* distances    = (const float*)d_in[1];
    const float* cache_hidden = (const float*)d_in[2];
    const float* hiddens      = (const float*)d_in[3];
    const float* W1           = (const float*)d_in[4];
    const float* b1           = (const float*)d_in[5];
    const float* W2           = (const float*)d_in[6];
    const float* b2           = (const float*)d_in[7];
    float* out = (float*)d_out;

    static int attr_set = 0;
    if (!attr_set) {
        cudaFuncSetAttribute(mu_calc_kernel,
                             cudaFuncAttributeMaxDynamicSharedMemorySize,
                             DYN_SMEM_BYTES);
        attr_set = 1;
    }
    mu_calc_kernel<<<GRID, NTHREADS, DYN_SMEM_BYTES>>>(vals, distances,
                                                       cache_hidden, hiddens,
                                                       W1, b1, W2, b2, out);
}